// round 10
// baseline (speedup 1.0000x reference)
#include <cuda_runtime.h>
#include <cuda_fp16.h>
#include <math.h>
#include <cstdint>

#define NROWS   131072
#define KEMB    512
#define DIM     64
#define HW      4096
#define OUT_ELEMS 8388608LL
#define TILE_M  128
#define NTILES  (NROWS / TILE_M)     // 1024
#define CTAS    148
#define THREADS 512
#define XS_R    132                  // channel-major stride (floats)
#define XS_BUF_F (DIM * XS_R)        // 8448 floats = 33792 B
#define SCORE_BIAS 512.0f
#define REFINE_MARGIN 0.35f

// smem offsets (bytes)
#define OFF_BFRAG 0                  // 64*2*32 uint4 = 65536
#define OFF_XS    65536              // 3 * 33792 = 101376
#define OFF_NVB   166912             // 512*4
#define OFF_NRMH  168960
#define OFF_NRML  171008
#define OFF_T3    173056             // 2(par) * 4 * 128 * 4 = 4096
#define OFF_CNT   177152             // 512*4
#define SMEM_TOTAL 179200

__device__ unsigned int g_counts[KEMB];
__device__ double g_sumsq;

__device__ __forceinline__ void mma16816h(float* c, const uint32_t* a, uint32_t b0, uint32_t b1) {
    asm volatile(
        "mma.sync.aligned.m16n8k16.row.col.f32.f16.f16.f32 "
        "{%0,%1,%2,%3}, {%4,%5,%6,%7}, {%8,%9}, {%0,%1,%2,%3};"
        : "+f"(c[0]), "+f"(c[1]), "+f"(c[2]), "+f"(c[3])
        : "r"(a[0]), "r"(a[1]), "r"(a[2]), "r"(a[3]), "r"(b0), "r"(b1));
}

__device__ __forceinline__ uint32_t packh2(float a, float b) {
    __half2 h = __floats2half2_rn(a, b);
    return *reinterpret_cast<uint32_t*>(&h);
}

__device__ __forceinline__ uint32_t smem_u32(const void* p) {
    uint32_t a;
    asm("{ .reg .u64 t; cvta.to.shared.u64 t, %1; cvt.u32.u64 %0, t; }" : "=r"(a) : "l"(p));
    return a;
}

// top-2 insert (packed u32: score-bits | idx; min = better)
#define T2_UPD(b1, b2, v) do { \
    uint32_t _t = max(b1, v); b1 = min(b1, v); b2 = min(b2, _t); } while (0)

// merge sorted pair (o1<=o2) into sorted pair (b1<=b2), keep top-2
#define T2_MERGE(b1, b2, o1, o2) do { \
    uint32_t _t = max(b1, o1); b1 = min(b1, o1); \
    uint32_t _u = min(b2, o2); b2 = min(_t, _u); } while (0)

// compensated accumulate of product x*e into (s,c)
#define CADD(s, c, xv, ev) do { \
    float _p  = __fmul_rn(xv, ev); \
    float _ep = fmaf(xv, ev, -_p); \
    float _z  = __fadd_rn(s, _p); \
    float _bv = __fsub_rn(_z, s); \
    float _er = __fadd_rn(__fsub_rn(s, __fsub_rn(_z, _bv)), __fsub_rn(_p, _bv)); \
    s = _z; c = __fadd_rn(c, __fadd_rn(_er, _ep)); } while (0)

// TwoSum-combine (so,co) into (s,c)
#define TWOSUM(s, c, so, co) do { \
    float _z = __fadd_rn(s, so); \
    float _bv = __fsub_rn(_z, s); \
    float _er = __fadd_rn(__fsub_rn(s, __fsub_rn(_z, _bv)), __fsub_rn(so, _bv)); \
    s = _z; c = __fadd_rn(__fadd_rn(c, co), _er); } while (0)

extern __shared__ char s_raw[];

__device__ __forceinline__ void stage_async(const float* __restrict__ gbase,
                                            uint32_t smem_dst, int tid) {
    #pragma unroll
    for (int p = 0; p < 4; p++) {
        int idx = tid + p * THREADS;        // 2048 chunks of 16B
        int c = idx >> 5, q = idx & 31;
        uint32_t s = smem_dst + (uint32_t)(c * XS_R + 4 * q) * 4u;
        const float* g = gbase + (size_t)c * HW + 4 * q;
        asm volatile("cp.async.cg.shared.global [%0], [%1], 16;" :: "r"(s), "l"(g) : "memory");
    }
    asm volatile("cp.async.commit_group;" ::: "memory");
}

__global__ void __launch_bounds__(THREADS, 1)
vq_main(const float* __restrict__ in, const float* __restrict__ emb,
        float* __restrict__ outq, float* __restrict__ outidx)
{
    char* sm = s_raw;
    uint4* bfrag = reinterpret_cast<uint4*>(sm + OFF_BFRAG);
    float* xsall = reinterpret_cast<float*>(sm + OFF_XS);
    float* nvb   = reinterpret_cast<float*>(sm + OFF_NVB);
    float* nrmh  = reinterpret_cast<float*>(sm + OFF_NRMH);
    float* nrml  = reinterpret_cast<float*>(sm + OFF_NRML);
    uint32_t* t3 = reinterpret_cast<uint32_t*>(sm + OFF_T3);     // [2][4][128]
    unsigned int* scnt = reinterpret_cast<unsigned int*>(sm + OFF_CNT);
    const uint32_t smb_xs = smem_u32(sm + OFF_XS);

    const int tid = threadIdx.x;
    const int wid = tid >> 5, lane = tid & 31;
    const int lq = lane >> 2, lr = lane & 3;
    const int rg = wid >> 1;            // mainloop row-group 0..7
    const int nh = wid & 1;             // codebook half

    double ssq_d = 0.0;

    // ---- one-time: B fragments, norms, counts ----
    for (int i = tid; i < 64 * 2 * 32; i += THREADS) {
        int ln = i & 31, kp = (i >> 5) & 1, ns = i >> 6;
        int n  = ns * 8 + (ln >> 2);
        int k0 = kp * 32 + (ln & 3) * 2;
        const float* er = emb + n * DIM;
        bfrag[i] = make_uint4(
            packh2(er[k0],      er[k0 + 1]),
            packh2(er[k0 + 8],  er[k0 + 9]),
            packh2(er[k0 + 16], er[k0 + 17]),
            packh2(er[k0 + 24], er[k0 + 25]));
    }
    for (int k = tid; k < KEMB; k += THREADS) {
        const float* e = emb + k * DIM;
        float s = 0.f, c = 0.f;
        #pragma unroll
        for (int d = 0; d < DIM; d++) CADD(s, c, e[d], e[d]);
        nrmh[k] = s; nrml[k] = c;
        nvb[k]  = s + SCORE_BIAS;
    }
    for (int i = tid; i < KEMB; i += THREADS) scnt[i] = 0u;

    // ---- prologue: stage first tile into buf 0 ----
    const int t0 = blockIdx.x;
    {
        const int b = t0 >> 5, hw0 = (t0 & 31) * TILE_M;
        stage_async(in + (size_t)b * (DIM * HW) + hw0, smb_xs, tid);
        asm volatile("cp.async.wait_all;" ::: "memory");
    }
    __syncthreads();

    int it = 0;
    for (int t = t0; t < NTILES; t += CTAS, it++) {
        const int cb = it - (it / 3) * 3;
        const float* xc = xsall + cb * XS_BUF_F;
        const int par = it & 1;

        // ---- A fragments from channel-major xs ----
        uint32_t a[4][4];
        {
            const int rl = rg * 16 + lq;
            #pragma unroll
            for (int ks = 0; ks < 4; ks++) {
                const int c0 = ks * 16 + lr * 2;
                const float* b0 = xc + c0 * XS_R;
                a[ks][0] = packh2(b0[rl],              b0[XS_R + rl]);
                a[ks][1] = packh2(b0[rl + 8],          b0[XS_R + rl + 8]);
                a[ks][2] = packh2(b0[8 * XS_R + rl],     b0[9 * XS_R + rl]);
                a[ks][3] = packh2(b0[8 * XS_R + rl + 8], b0[9 * XS_R + rl + 8]);
            }
        }

        // ---- prefetch next tile ----
        const int tn = t + CTAS;
        if (tn < NTILES) {
            const int nb = (it + 1) - ((it + 1) / 3) * 3;
            const int b = tn >> 5, hw0 = (tn & 31) * TILE_M;
            stage_async(in + (size_t)b * (DIM * HW) + hw0,
                        smb_xs + (uint32_t)nb * 33792u, tid);
        }

        // ---- main loop: 32 n-steps, top-2 per row per lane ----
        uint32_t b1a = 0xFFFFFFFFu, b2a = 0xFFFFFFFFu;
        uint32_t b1b = 0xFFFFFFFFu, b2b = 0xFFFFFFFFu;
        const int ns0 = nh * 32;
        #pragma unroll 2
        for (int nsi = 0; nsi < 32; nsi++) {
            const int ns = ns0 + nsi;
            uint4 bA = bfrag[(ns * 2 + 0) * 32 + lane];
            uint4 bB = bfrag[(ns * 2 + 1) * 32 + lane];
            float acc01[4] = {0.f, 0.f, 0.f, 0.f};
            float acc23[4] = {0.f, 0.f, 0.f, 0.f};
            mma16816h(acc01, a[0], bA.x, bA.y);
            mma16816h(acc23, a[2], bB.x, bB.y);
            mma16816h(acc01, a[1], bA.z, bA.w);
            mma16816h(acc23, a[3], bB.z, bB.w);

            const int ka = ns * 8 + lr * 2;
            float2 nv = *reinterpret_cast<const float2*>(nvb + ka);
            float s0 = fmaf(-2.f, acc01[0] + acc23[0], nv.x);
            float s1 = fmaf(-2.f, acc01[1] + acc23[1], nv.y);
            float s2 = fmaf(-2.f, acc01[2] + acc23[2], nv.x);
            float s3 = fmaf(-2.f, acc01[3] + acc23[3], nv.y);
            uint32_t u0 = (__float_as_uint(s0) & 0xFFFFFE00u) | (uint32_t)ka;
            uint32_t u1 = (__float_as_uint(s1) & 0xFFFFFE00u) | (uint32_t)(ka + 1);
            uint32_t u2 = (__float_as_uint(s2) & 0xFFFFFE00u) | (uint32_t)ka;
            uint32_t u3 = (__float_as_uint(s3) & 0xFFFFFE00u) | (uint32_t)(ka + 1);
            T2_UPD(b1a, b2a, u0);
            T2_UPD(b1a, b2a, u1);
            T2_UPD(b1b, b2b, u2);
            T2_UPD(b1b, b2b, u3);
        }

        // ---- merge across 4 lanes sharing each row; write t3[par] ----
        #pragma unroll
        for (int off = 1; off <= 2; off <<= 1) {
            uint32_t o1 = __shfl_xor_sync(0xffffffffu, b1a, off);
            uint32_t o2 = __shfl_xor_sync(0xffffffffu, b2a, off);
            T2_MERGE(b1a, b2a, o1, o2);
            o1 = __shfl_xor_sync(0xffffffffu, b1b, off);
            o2 = __shfl_xor_sync(0xffffffffu, b2b, off);
            T2_MERGE(b1b, b2b, o1, o2);
        }
        if (lr == 0) {
            uint32_t* tp = t3 + par * 512;
            int ra = rg * 16 + lq, rb = ra + 8;
            tp[(nh * 2 + 0) * 128 + ra] = b1a;
            tp[(nh * 2 + 1) * 128 + ra] = b2a;
            tp[(nh * 2 + 0) * 128 + rb] = b1b;
            tp[(nh * 2 + 1) * 128 + rb] = b2b;
        }

        asm volatile("cp.async.wait_all;" ::: "memory");
        __syncthreads();

        // ---- epilogue: every warp owns 8 rows, 4 lanes per row ----
        {
            const int r  = wid * 8 + (lane >> 2);
            const int sl = lane & 3;
            const uint32_t* tp = t3 + par * 512;
            uint32_t u1 = tp[r],       u2 = tp[128 + r];
            uint32_t o1 = tp[256 + r], o2 = tp[384 + r];
            // top-3 of the two sorted pairs
            uint32_t tt = max(u1, o1), m1 = min(u1, o1);
            uint32_t uu = min(u2, o2), vv = max(u2, o2);
            uint32_t m2 = min(tt, uu);
            uint32_t m3 = min(max(tt, uu), vv);

            // load this lane's 16 channels of x (bank-staggered)
            const float* xcol = xc + r;
            float x[16];
            #pragma unroll
            for (int j = 0; j < 16; j++) {
                int i = (j + 2 * sl) & 15;
                x[i] = xcol[(sl * 16 + i) * XS_R];
            }

            int fbi = (int)(m1 & 511u);
            float s1f = __uint_as_float(m1 & 0xFFFFFE00u);
            float s2f = __uint_as_float(m2 & 0xFFFFFE00u);
            bool need = (s2f - s1f < REFINE_MARGIN);
            if (__any_sync(0xffffffffu, need)) {
                int c0 = fbi, c1 = (int)(m2 & 511u), c2 = (int)(m3 & 511u);
                float ds0 = 0.f, dc0 = 0.f, ds1 = 0.f, dc1 = 0.f, ds2 = 0.f, dc2 = 0.f;
                const float* e0 = emb + c0 * DIM + sl * 16;
                const float* e1 = emb + c1 * DIM + sl * 16;
                const float* e2 = emb + c2 * DIM + sl * 16;
                #pragma unroll
                for (int v = 0; v < 4; v++) {
                    float4 q0 = reinterpret_cast<const float4*>(e0)[v];
                    float4 q1 = reinterpret_cast<const float4*>(e1)[v];
                    float4 q2 = reinterpret_cast<const float4*>(e2)[v];
                    CADD(ds0, dc0, x[4*v+0], q0.x); CADD(ds0, dc0, x[4*v+1], q0.y);
                    CADD(ds0, dc0, x[4*v+2], q0.z); CADD(ds0, dc0, x[4*v+3], q0.w);
                    CADD(ds1, dc1, x[4*v+0], q1.x); CADD(ds1, dc1, x[4*v+1], q1.y);
                    CADD(ds1, dc1, x[4*v+2], q1.z); CADD(ds1, dc1, x[4*v+3], q1.w);
                    CADD(ds2, dc2, x[4*v+0], q2.x); CADD(ds2, dc2, x[4*v+1], q2.y);
                    CADD(ds2, dc2, x[4*v+2], q2.z); CADD(ds2, dc2, x[4*v+3], q2.w);
                }
                // exact cross-lane combine within each 4-lane group
                #pragma unroll
                for (int off = 1; off <= 2; off <<= 1) {
                    float so, co;
                    so = __shfl_xor_sync(0xffffffffu, ds0, off);
                    co = __shfl_xor_sync(0xffffffffu, dc0, off);
                    TWOSUM(ds0, dc0, so, co);
                    so = __shfl_xor_sync(0xffffffffu, ds1, off);
                    co = __shfl_xor_sync(0xffffffffu, dc1, off);
                    TWOSUM(ds1, dc1, so, co);
                    so = __shfl_xor_sync(0xffffffffu, ds2, off);
                    co = __shfl_xor_sync(0xffffffffu, dc2, off);
                    TWOSUM(ds2, dc2, so, co);
                }
                if (need) {
                    double d0 = ((double)nrmh[c0] + (double)nrml[c0]) - 2.0 * ((double)ds0 + (double)dc0);
                    double d1 = ((double)nrmh[c1] + (double)nrml[c1]) - 2.0 * ((double)ds1 + (double)dc1);
                    double d2 = ((double)nrmh[c2] + (double)nrml[c2]) - 2.0 * ((double)ds2 + (double)dc2);
                    double bd = d0; int bi = c0;
                    if (d1 < bd || (d1 == bd && c1 < bi)) { bd = d1; bi = c1; }
                    if (d2 < bd || (d2 == bd && c2 < bi)) { bd = d2; bi = c2; }
                    fbi = bi;
                }
            }

            const int rowg = t * TILE_M + r;
            const int bb = rowg >> 12, hw = rowg & (HW - 1);
            if (sl == 0) {
                atomicAdd(&scnt[fbi], 1u);
                if (outidx) outidx[rowg] = (float)fbi;
            }

            float* xout = outq + (size_t)bb * (DIM * HW) + hw + (size_t)(sl * 16) * HW;
            const float4* q4 = reinterpret_cast<const float4*>(emb + fbi * DIM + sl * 16);
            float ssq = 0.f;
            #pragma unroll
            for (int v = 0; v < 4; v++) {
                float4 q = q4[v];
                float d0 = q.x - x[4*v+0], d1 = q.y - x[4*v+1];
                float d2 = q.z - x[4*v+2], d3 = q.w - x[4*v+3];
                xout[(size_t)(4*v+0) * HW] = x[4*v+0] + d0;
                xout[(size_t)(4*v+1) * HW] = x[4*v+1] + d1;
                xout[(size_t)(4*v+2) * HW] = x[4*v+2] + d2;
                xout[(size_t)(4*v+3) * HW] = x[4*v+3] + d3;
                ssq = fmaf(d0, d0, ssq); ssq = fmaf(d1, d1, ssq);
                ssq = fmaf(d2, d2, ssq); ssq = fmaf(d3, d3, ssq);
            }
            ssq_d += (double)ssq;
        }
    }

    // ---- final reductions ----
    #pragma unroll
    for (int off = 16; off > 0; off >>= 1)
        ssq_d += __shfl_xor_sync(0xffffffffu, ssq_d, off);
    if (lane == 0) atomicAdd(&g_sumsq, ssq_d);

    __syncthreads();
    for (int i = tid; i < KEMB; i += THREADS)
        if (scnt[i]) atomicAdd(&g_counts[i], scnt[i]);
}

__global__ void vq_fin(float* loss_ptr, float* perp_ptr) {
    __shared__ float red[KEMB];
    const int t = threadIdx.x;
    float p = (float)g_counts[t] * (1.0f / (float)NROWS);
    red[t] = p * logf(p + 1e-10f);
    __syncthreads();
    #pragma unroll
    for (int s = KEMB / 2; s > 0; s >>= 1) {
        if (t < s) red[t] += red[t + s];
        __syncthreads();
    }
    if (t == 0) {
        if (perp_ptr) *perp_ptr = expf(-red[0]);
        if (loss_ptr) *loss_ptr = 0.25f * (float)(g_sumsq / (double)OUT_ELEMS);
        g_sumsq = 0.0;
    }
    g_counts[t] = 0u;
}

__global__ void vq_nop() {}

extern "C" void kernel_launch(void* const* d_in, const int* in_sizes, int n_in,
                              void* d_out, int out_size) {
    const float* in  = (const float*)d_in[0];
    const float* emb = (const float*)d_in[1];
    float* out = (float*)d_out;

    float* lossp = nullptr; float* perpp = nullptr; float* idxp = nullptr;
    float* outq = out;
    if ((long long)out_size == OUT_ELEMS) {
        outq = out;
    } else {
        lossp = out;
        outq  = out + 1;
        perpp = out + 1 + OUT_ELEMS;
        idxp  = perpp + 1;
    }

    cudaFuncSetAttribute(vq_main, cudaFuncAttributeMaxDynamicSharedMemorySize, SMEM_TOTAL);

    vq_main<<<CTAS, THREADS, SMEM_TOTAL>>>(in, emb, outq, idxp);
    vq_fin<<<1, KEMB>>>(lossp, perpp);
    vq_nop<<<1, 32>>>();
}

// round 11
// speedup vs baseline: 1.2269x; 1.2269x over previous
#include <cuda_runtime.h>
#include <cuda_fp16.h>
#include <math.h>
#include <cstdint>

#define NROWS   131072
#define KEMB    512
#define DIM     64
#define HW      4096
#define OUT_ELEMS 8388608LL
#define TILE_M  128
#define NTILES  (NROWS / TILE_M)     // 1024
#define CTAS    148
#define THREADS 512
#define XS_R    132                  // channel-major stride (floats)
#define XS_BUF_F (DIM * XS_R)        // 8448 floats = 33792 B
#define SCORE_BIAS 512.0f
#define REFINE_MARGIN 0.35f

// smem offsets (bytes)
#define OFF_BFRAG 0                  // 64*2*32 uint4 = 65536
#define OFF_XS    65536              // 3 * 33792 = 101376
#define OFF_NVB   166912             // 512*4
#define OFF_NRMH  168960
#define OFF_NRML  171008
#define OFF_T3    173056             // 2(par) * 4 * 128 * 4 = 4096
#define OFF_CNT   177152             // 512*4
#define SMEM_TOTAL 179200

__device__ unsigned int g_counts[KEMB];
__device__ double g_sumsq;

__device__ __forceinline__ void mma16816h(float* c, const uint32_t* a, uint32_t b0, uint32_t b1) {
    asm volatile(
        "mma.sync.aligned.m16n8k16.row.col.f32.f16.f16.f32 "
        "{%0,%1,%2,%3}, {%4,%5,%6,%7}, {%8,%9}, {%0,%1,%2,%3};"
        : "+f"(c[0]), "+f"(c[1]), "+f"(c[2]), "+f"(c[3])
        : "r"(a[0]), "r"(a[1]), "r"(a[2]), "r"(a[3]), "r"(b0), "r"(b1));
}

__device__ __forceinline__ uint32_t packh2(float a, float b) {
    __half2 h = __floats2half2_rn(a, b);
    return *reinterpret_cast<uint32_t*>(&h);
}

__device__ __forceinline__ uint32_t smem_u32(const void* p) {
    uint32_t a;
    asm("{ .reg .u64 t; cvta.to.shared.u64 t, %1; cvt.u32.u64 %0, t; }" : "=r"(a) : "l"(p));
    return a;
}

// top-2 insert (packed u32: score-bits | idx; min = better)
#define T2_UPD(b1, b2, v) do { \
    uint32_t _t = max(b1, v); b1 = min(b1, v); b2 = min(b2, _t); } while (0)

// merge sorted pair (o1<=o2) into sorted pair (b1<=b2), keep top-2
#define T2_MERGE(b1, b2, o1, o2) do { \
    uint32_t _t = max(b1, o1); b1 = min(b1, o1); \
    uint32_t _u = min(b2, o2); b2 = min(_t, _u); } while (0)

// compensated fp32 dot, x strided by XS_R (near-exact ~1e-13)
__device__ __forceinline__ void comp_dot_s(const float* __restrict__ xp,
                                           const float* __restrict__ e,
                                           float& s_out, float& c_out) {
    float s = 0.f, c = 0.f;
    #pragma unroll
    for (int d = 0; d < DIM; d++) {
        float xd = xp[d * XS_R];
        float p  = __fmul_rn(xd, e[d]);
        float ep = fmaf(xd, e[d], -p);
        float z  = __fadd_rn(s, p);
        float bv = __fsub_rn(z, s);
        float err = __fadd_rn(__fsub_rn(s, __fsub_rn(z, bv)), __fsub_rn(p, bv));
        s = z;
        c = __fadd_rn(c, __fadd_rn(err, ep));
    }
    s_out = s; c_out = c;
}

extern __shared__ char s_raw[];

__device__ __forceinline__ void stage_async(const float* __restrict__ gbase,
                                            uint32_t smem_dst, int tid) {
    #pragma unroll
    for (int p = 0; p < 4; p++) {
        int idx = tid + p * THREADS;        // 2048 chunks of 16B
        int c = idx >> 5, q = idx & 31;
        uint32_t s = smem_dst + (uint32_t)(c * XS_R + 4 * q) * 4u;
        const float* g = gbase + (size_t)c * HW + 4 * q;
        asm volatile("cp.async.cg.shared.global [%0], [%1], 16;" :: "r"(s), "l"(g) : "memory");
    }
    asm volatile("cp.async.commit_group;" ::: "memory");
}

__global__ void __launch_bounds__(THREADS, 1)
vq_main(const float* __restrict__ in, const float* __restrict__ emb,
        float* __restrict__ outq, float* __restrict__ outidx)
{
    char* sm = s_raw;
    uint4* bfrag = reinterpret_cast<uint4*>(sm + OFF_BFRAG);
    float* xsall = reinterpret_cast<float*>(sm + OFF_XS);
    float* nvb   = reinterpret_cast<float*>(sm + OFF_NVB);
    float* nrmh  = reinterpret_cast<float*>(sm + OFF_NRMH);
    float* nrml  = reinterpret_cast<float*>(sm + OFF_NRML);
    uint32_t* t3 = reinterpret_cast<uint32_t*>(sm + OFF_T3);     // [2][4][128]
    unsigned int* scnt = reinterpret_cast<unsigned int*>(sm + OFF_CNT);
    const uint32_t smb_xs = smem_u32(sm + OFF_XS);

    const int tid = threadIdx.x;
    const int wid = tid >> 5, lane = tid & 31;
    const int lq = lane >> 2, lr = lane & 3;
    const int rg = wid >> 1;            // row-group 0..7
    const int nh = wid & 1;             // codebook half

    // ---- one-time: B fragments, norms, counts ----
    for (int i = tid; i < 64 * 2 * 32; i += THREADS) {
        int ln = i & 31, kp = (i >> 5) & 1, ns = i >> 6;
        int n  = ns * 8 + (ln >> 2);
        int k0 = kp * 32 + (ln & 3) * 2;
        const float* er = emb + n * DIM;
        bfrag[i] = make_uint4(
            packh2(er[k0],      er[k0 + 1]),
            packh2(er[k0 + 8],  er[k0 + 9]),
            packh2(er[k0 + 16], er[k0 + 17]),
            packh2(er[k0 + 24], er[k0 + 25]));
    }
    for (int k = tid; k < KEMB; k += THREADS) {
        const float* e = emb + k * DIM;
        float s = 0.f, c = 0.f;
        #pragma unroll
        for (int d = 0; d < DIM; d++) {
            float p  = __fmul_rn(e[d], e[d]);
            float ep = fmaf(e[d], e[d], -p);
            float z  = __fadd_rn(s, p);
            float bv = __fsub_rn(z, s);
            float err = __fadd_rn(__fsub_rn(s, __fsub_rn(z, bv)), __fsub_rn(p, bv));
            s = z;
            c = __fadd_rn(c, __fadd_rn(err, ep));
        }
        nrmh[k] = s; nrml[k] = c;
        nvb[k]  = s + SCORE_BIAS;
    }
    for (int i = tid; i < KEMB; i += THREADS) scnt[i] = 0u;

    // ---- prologue: stage first tile into buf 0 ----
    const int t0 = blockIdx.x;
    {
        const int b = t0 >> 5, hw0 = (t0 & 31) * TILE_M;
        stage_async(in + (size_t)b * (DIM * HW) + hw0, smb_xs, tid);
        asm volatile("cp.async.wait_all;" ::: "memory");
    }
    __syncthreads();

    int it = 0;
    for (int t = t0; t < NTILES; t += CTAS, it++) {
        const int cb = it - (it / 3) * 3;
        const float* xc = xsall + cb * XS_BUF_F;
        const int par = it & 1;

        // ---- A fragments from channel-major xs ----
        uint32_t a[4][4];
        {
            const int rl = rg * 16 + lq;
            #pragma unroll
            for (int ks = 0; ks < 4; ks++) {
                const int c0 = ks * 16 + lr * 2;
                const float* b0 = xc + c0 * XS_R;
                a[ks][0] = packh2(b0[rl],              b0[XS_R + rl]);
                a[ks][1] = packh2(b0[rl + 8],          b0[XS_R + rl + 8]);
                a[ks][2] = packh2(b0[8 * XS_R + rl],     b0[9 * XS_R + rl]);
                a[ks][3] = packh2(b0[8 * XS_R + rl + 8], b0[9 * XS_R + rl + 8]);
            }
        }

        // ---- prefetch next tile (hidden under mainloop) ----
        const int tn = t + CTAS;
        if (tn < NTILES) {
            const int nb = (it + 1) - ((it + 1) / 3) * 3;
            const int b = tn >> 5, hw0 = (tn & 31) * TILE_M;
            stage_async(in + (size_t)b * (DIM * HW) + hw0,
                        smb_xs + (uint32_t)nb * 33792u, tid);
        }

        // ---- main loop: this warp's 32 n-steps, top-2 per row ----
        uint32_t b1a = 0xFFFFFFFFu, b2a = 0xFFFFFFFFu;
        uint32_t b1b = 0xFFFFFFFFu, b2b = 0xFFFFFFFFu;
        const int ns0 = nh * 32;
        #pragma unroll 2
        for (int nsi = 0; nsi < 32; nsi++) {
            const int ns = ns0 + nsi;
            uint4 bA = bfrag[(ns * 2 + 0) * 32 + lane];
            uint4 bB = bfrag[(ns * 2 + 1) * 32 + lane];
            float acc01[4] = {0.f, 0.f, 0.f, 0.f};
            float acc23[4] = {0.f, 0.f, 0.f, 0.f};
            mma16816h(acc01, a[0], bA.x, bA.y);
            mma16816h(acc23, a[2], bB.x, bB.y);
            mma16816h(acc01, a[1], bA.z, bA.w);
            mma16816h(acc23, a[3], bB.z, bB.w);

            const int ka = ns * 8 + lr * 2;
            float2 nv = *reinterpret_cast<const float2*>(nvb + ka);
            float s0 = fmaf(-2.f, acc01[0] + acc23[0], nv.x);
            float s1 = fmaf(-2.f, acc01[1] + acc23[1], nv.y);
            float s2 = fmaf(-2.f, acc01[2] + acc23[2], nv.x);
            float s3 = fmaf(-2.f, acc01[3] + acc23[3], nv.y);
            uint32_t u0 = (__float_as_uint(s0) & 0xFFFFFE00u) | (uint32_t)ka;
            uint32_t u1 = (__float_as_uint(s1) & 0xFFFFFE00u) | (uint32_t)(ka + 1);
            uint32_t u2 = (__float_as_uint(s2) & 0xFFFFFE00u) | (uint32_t)ka;
            uint32_t u3 = (__float_as_uint(s3) & 0xFFFFFE00u) | (uint32_t)(ka + 1);
            T2_UPD(b1a, b2a, u0);
            T2_UPD(b1a, b2a, u1);
            T2_UPD(b1b, b2b, u2);
            T2_UPD(b1b, b2b, u3);
        }

        // ---- merge across 4 lanes sharing each row; write t3[par] ----
        #pragma unroll
        for (int off = 1; off <= 2; off <<= 1) {
            uint32_t o1 = __shfl_xor_sync(0xffffffffu, b1a, off);
            uint32_t o2 = __shfl_xor_sync(0xffffffffu, b2a, off);
            T2_MERGE(b1a, b2a, o1, o2);
            o1 = __shfl_xor_sync(0xffffffffu, b1b, off);
            o2 = __shfl_xor_sync(0xffffffffu, b2b, off);
            T2_MERGE(b1b, b2b, o1, o2);
        }
        if (lr == 0) {
            uint32_t* tp = t3 + par * 512;
            int ra = rg * 16 + lq, rb = ra + 8;
            tp[(nh * 2 + 0) * 128 + ra] = b1a;
            tp[(nh * 2 + 1) * 128 + ra] = b2a;
            tp[(nh * 2 + 0) * 128 + rb] = b1b;
            tp[(nh * 2 + 1) * 128 + rb] = b2b;
        }

        asm volatile("cp.async.wait_all;" ::: "memory");
        __syncthreads();   // t3[par] visible; next xs buffer complete

        // ---- fused epilogue (tid<128); other warps race into next tile ----
        if (tid < TILE_M) {
            const int r = tid;
            const uint32_t* tp = t3 + par * 512;
            uint32_t u1 = tp[r],       u2 = tp[128 + r];
            uint32_t o1 = tp[256 + r], o2 = tp[384 + r];
            // top-3 of the union of the two sorted pairs
            uint32_t m1 = min(u1, o1), tt = max(u1, o1);
            uint32_t uu = min(u2, o2), vv = max(u2, o2);
            uint32_t m2 = min(tt, uu);
            uint32_t m3 = min(max(tt, uu), vv);

            float s1f = __uint_as_float(m1 & 0xFFFFFE00u);
            float s2f = __uint_as_float(m2 & 0xFFFFFE00u);
            int i1 = (int)(m1 & 511u), i2 = (int)(m2 & 511u), i3 = (int)(m3 & 511u);
            int fbi = i1;
            if (s2f - s1f < REFINE_MARGIN) {
                const float* xp = xc + r;
                int cand[3] = {i1, i2, i3};
                double bestd = 1e300; int besti = 0x7fffffff;
                #pragma unroll
                for (int c = 0; c < 3; c++) {
                    int k = cand[c];
                    float ds, dc;
                    comp_dot_s(xp, emb + k * DIM, ds, dc);
                    double d = ((double)nrmh[k] + (double)nrml[k])
                             - 2.0 * ((double)ds + (double)dc);
                    if (d < bestd || (d == bestd && k < besti)) { bestd = d; besti = k; }
                }
                fbi = besti;
            }
            atomicAdd(&scnt[fbi], 1u);

            const int rowg = t * TILE_M + r;
            const int bb = rowg >> 12, hw = rowg & (HW - 1);
            if (outidx) outidx[rowg] = (float)fbi;

            float* xout = outq + (size_t)bb * (DIM * HW) + hw;
            const float4* q4 = reinterpret_cast<const float4*>(emb + fbi * DIM);
            const float* xcol = xc + r;
            float ssq = 0.f;
            #pragma unroll
            for (int i = 0; i < 16; i++) {
                float4 q = q4[i];
                float x0 = xcol[(4 * i + 0) * XS_R];
                float x1 = xcol[(4 * i + 1) * XS_R];
                float x2 = xcol[(4 * i + 2) * XS_R];
                float x3 = xcol[(4 * i + 3) * XS_R];
                float d0 = q.x - x0, d1 = q.y - x1, d2 = q.z - x2, d3 = q.w - x3;
                xout[(size_t)(4 * i + 0) * HW] = x0 + d0;
                xout[(size_t)(4 * i + 1) * HW] = x1 + d1;
                xout[(size_t)(4 * i + 2) * HW] = x2 + d2;
                xout[(size_t)(4 * i + 3) * HW] = x3 + d3;
                ssq = fmaf(d0, d0, ssq); ssq = fmaf(d1, d1, ssq);
                ssq = fmaf(d2, d2, ssq); ssq = fmaf(d3, d3, ssq);
            }
            #pragma unroll
            for (int off = 16; off > 0; off >>= 1)
                ssq += __shfl_down_sync(0xffffffffu, ssq, off);
            if (lane == 0) atomicAdd(&g_sumsq, (double)ssq);
        }
    }

    // flush per-CTA histogram
    __syncthreads();
    for (int i = tid; i < KEMB; i += THREADS)
        if (scnt[i]) atomicAdd(&g_counts[i], scnt[i]);
}

// fin: compute loss/perplexity, then reset globals for the next (graph) call
__global__ void vq_fin(float* loss_ptr, float* perp_ptr) {
    __shared__ float red[KEMB];
    const int t = threadIdx.x;
    float p = (float)g_counts[t] * (1.0f / (float)NROWS);
    red[t] = p * logf(p + 1e-10f);
    __syncthreads();
    #pragma unroll
    for (int s = KEMB / 2; s > 0; s >>= 1) {
        if (t < s) red[t] += red[t + s];
        __syncthreads();
    }
    if (t == 0) {
        if (perp_ptr) *perp_ptr = expf(-red[0]);
        if (loss_ptr) *loss_ptr = 0.25f * (float)(g_sumsq / (double)OUT_ELEMS);
        g_sumsq = 0.0;
    }
    g_counts[t] = 0u;
}

__global__ void vq_nop() {}

extern "C" void kernel_launch(void* const* d_in, const int* in_sizes, int n_in,
                              void* d_out, int out_size) {
    const float* in  = (const float*)d_in[0];
    const float* emb = (const float*)d_in[1];
    float* out = (float*)d_out;

    float* lossp = nullptr; float* perpp = nullptr; float* idxp = nullptr;
    float* outq = out;
    if ((long long)out_size == OUT_ELEMS) {
        outq = out;
    } else {
        lossp = out;
        outq  = out + 1;
        perpp = out + 1 + OUT_ELEMS;
        idxp  = perpp + 1;
    }

    cudaFuncSetAttribute(vq_main, cudaFuncAttributeMaxDynamicSharedMemorySize, SMEM_TOTAL);

    vq_main<<<CTAS, THREADS, SMEM_TOTAL>>>(in, emb, outq, idxp);
    vq_fin<<<1, KEMB>>>(lossp, perpp);
    vq_nop<<<1, 32>>>();
}